// round 3
// baseline (speedup 1.0000x reference)
#include <cuda_runtime.h>
#include <cstdint>

#define NB 128
#define CIN 256
#define HH 28
#define WW 28
#define HWPIX 784
#define PW 30
#define PROWS 960
#define TAPS 9

#define BM 128
#define BN 256
#define BK 128
#define KBLOCKS 18
#define STAGES 3
#define TPB 256

#define A_BYTES (BM * BK)          // 16384
#define B_BYTES (BN * BK)          // 32768
#define STG_BYTES (A_BYTES + B_BYTES)  // 49152
#define SMEM_TOTAL (STAGES * STG_BYTES)

__device__ __align__(16) int8_t g_xpad[(size_t)NB * PROWS * CIN];  // padded NHWC signs
__device__ __align__(16) int8_t g_wmat[(size_t)CIN * TAPS * CIN];  // [co][tap*256+ci]
__device__ float g_scale[CIN];
__device__ float g_bias[CIN];

// ---------------- helpers ----------------
__device__ __forceinline__ uint32_t smem_u32(const void* p) {
    uint32_t a;
    asm("{ .reg .u64 t; cvta.to.shared.u64 t, %1; cvt.u32.u64 %0, t; }" : "=r"(a) : "l"(p));
    return a;
}

#define CP_ASYNC16(dst, src) \
    asm volatile("cp.async.cg.shared.global [%0], [%1], 16;" :: "r"(dst), "l"(src))
#define CP_COMMIT() asm volatile("cp.async.commit_group;" ::: "memory")
#define CP_WAIT(n)  asm volatile("cp.async.wait_group %0;" :: "n"(n) : "memory")

__device__ __forceinline__ void ldsm_x4(uint32_t* r, uint32_t addr) {
    asm volatile("ldmatrix.sync.aligned.m8n8.x4.shared.b16 {%0,%1,%2,%3}, [%4];"
                 : "=r"(r[0]), "=r"(r[1]), "=r"(r[2]), "=r"(r[3]) : "r"(addr));
}
__device__ __forceinline__ void ldsm_x2(uint32_t* r, uint32_t addr) {
    asm volatile("ldmatrix.sync.aligned.m8n8.x2.shared.b16 {%0,%1}, [%2];"
                 : "=r"(r[0]), "=r"(r[1]) : "r"(addr));
}
__device__ __forceinline__ void mma_s8(int* c, const uint32_t* a, const uint32_t* b) {
    asm volatile(
        "mma.sync.aligned.m16n8k32.row.col.s32.s8.s8.s32 "
        "{%0,%1,%2,%3}, {%4,%5,%6,%7}, {%8,%9}, {%0,%1,%2,%3};"
        : "+r"(c[0]), "+r"(c[1]), "+r"(c[2]), "+r"(c[3])
        : "r"(a[0]), "r"(a[1]), "r"(a[2]), "r"(a[3]), "r"(b[0]), "r"(b[1]));
}

// ---------------- prep kernels ----------------
__global__ void zero_xpad_kernel() {
    size_t i = (size_t)blockIdx.x * 256 + threadIdx.x;
    ((uint4*)g_xpad)[i] = make_uint4(0, 0, 0, 0);
}

__global__ void pack_x_kernel(const float* __restrict__ x) {
    int n = blockIdx.x, h = blockIdx.y, ci = threadIdx.x;
    const float* xp = x + ((size_t)(n * CIN + ci) * HH + h) * WW;
    int8_t* dst = g_xpad + ((size_t)n * PROWS + (size_t)(h + 1) * PW + 1) * CIN + ci;
#pragma unroll
    for (int w = 0; w < WW; w++) {
        float v = xp[w];
        dst[(size_t)w * CIN] = (v < 0.f) ? (int8_t)-1 : (v > 0.f ? (int8_t)1 : (int8_t)0);
    }
}

__global__ void pack_w_kernel(const float* __restrict__ w) {
    int co = blockIdx.x, ci = threadIdx.x;
    const float* wp = w + (size_t)(co * CIN + ci) * TAPS;
#pragma unroll
    for (int t = 0; t < TAPS; t++) {
        float v = wp[t];
        g_wmat[(size_t)co * (TAPS * CIN) + t * CIN + ci] =
            (v < 0.f) ? (int8_t)-1 : (v > 0.f ? (int8_t)1 : (int8_t)0);
    }
}

__global__ void bn_prep_kernel(const float* __restrict__ gamma, const float* __restrict__ beta,
                               const float* __restrict__ mean, const float* __restrict__ var) {
    int c = threadIdx.x;
    float inv = gamma[c] * rsqrtf(var[c] + 1e-5f);
    g_scale[c] = inv;
    g_bias[c] = beta[c] - mean[c] * inv;
}

// ---------------- loader: one K-block (tap, ch-half) into a stage ----------------
__device__ __forceinline__ void load_block(uint32_t stage, int n, int p0, int kb, int tid) {
    int t = kb >> 1, cb = kb & 1;
    int kh = t / 3, kw = t - kh * 3;
    int shift = (kh - 1) * PW + (kw - 1);
    const int8_t* abase = g_xpad + ((size_t)n * PROWS + p0 + shift) * CIN + cb * 128;
    // A: 128 rows x 128B
#pragma unroll
    for (int it = 0; it < 4; it++) {
        int ch = tid + it * 256;
        int row = ch >> 3, c = ch & 7;
        const int8_t* src = abase + (size_t)row * CIN + c * 16;
        uint32_t dst = stage + row * 128 + ((c ^ (row & 7)) << 4);
        CP_ASYNC16(dst, __cvta_generic_to_global(src));
    }
    // B: 256 rows x 128B
    const int8_t* bbase = g_wmat + t * CIN + cb * 128;
#pragma unroll
    for (int it = 0; it < 8; it++) {
        int ch = tid + it * 256;
        int row = ch >> 3, c = ch & 7;
        const int8_t* src = bbase + (size_t)row * (TAPS * CIN) + c * 16;
        uint32_t dst = stage + A_BYTES + row * 128 + ((c ^ (row & 7)) << 4);
        CP_ASYNC16(dst, __cvta_generic_to_global(src));
    }
}

// ---------------- main kernel ----------------
__global__ __launch_bounds__(TPB, 1)
void imma_conv_kernel(const float* __restrict__ x, float* __restrict__ out) {
    extern __shared__ __align__(1024) char smem[];
    uint32_t sb = smem_u32(smem);
    int tid = threadIdx.x;
    int lane = tid & 31, wid = tid >> 5;
    int warp_m = wid >> 2, warp_n = wid & 3;
    int n = blockIdx.x;
    int p0 = 31 + blockIdx.y * BM;

    // per-thread ldmatrix address components
    int s = lane & 7;                                   // swizzle key (row & 7)
    int rowA_l = (lane & 7) + ((lane >> 3) & 1) * 8;    // x4: matrix row
    int cbitA = (lane >> 4) & 1;                        // x4: chunk select
    int rowB_l = lane & 7;                              // x2
    int cbitB = (lane >> 3) & 1;

    uint32_t aOff[4], bOff[8];
#pragma unroll
    for (int mi = 0; mi < 4; mi++)
        aOff[mi] = (warp_m * 64 + mi * 16 + rowA_l) * 128;
#pragma unroll
    for (int ni = 0; ni < 8; ni++)
        bOff[ni] = A_BYTES + (warp_n * 64 + ni * 8 + rowB_l) * 128;

    int acc[4][8][4];
#pragma unroll
    for (int mi = 0; mi < 4; mi++)
#pragma unroll
        for (int ni = 0; ni < 8; ni++)
#pragma unroll
            for (int r = 0; r < 4; r++) acc[mi][ni][r] = 0;

    // prologue
#pragma unroll
    for (int i = 0; i < STAGES; i++) {
        load_block(sb + i * STG_BYTES, n, p0, i, tid);
        CP_COMMIT();
    }

    for (int i = 0; i < KBLOCKS; i++) {
        uint32_t stg = sb + (i % STAGES) * STG_BYTES;
        CP_WAIT(2);
        __syncthreads();
#pragma unroll
        for (int kk = 0; kk < 4; kk++) {
            uint32_t a[4][4];
#pragma unroll
            for (int mi = 0; mi < 4; mi++)
                ldsm_x4(a[mi], stg + aOff[mi] + ((((kk * 2) + cbitA) ^ s) << 4));
            uint32_t b[8][2];
#pragma unroll
            for (int ni = 0; ni < 8; ni++)
                ldsm_x2(b[ni], stg + bOff[ni] + ((((kk * 2) + cbitB) ^ s) << 4));
#pragma unroll
            for (int mi = 0; mi < 4; mi++)
#pragma unroll
                for (int ni = 0; ni < 8; ni++)
                    mma_s8(acc[mi][ni], a[mi], b[ni]);
        }
        __syncthreads();
        if (i + STAGES < KBLOCKS)
            load_block(stg, n, p0, i + STAGES, tid);
        CP_COMMIT();
    }

    // epilogue: BN + hardtanh + residual
    int g = lane >> 2, tig = lane & 3;
#pragma unroll
    for (int mi = 0; mi < 4; mi++) {
        int pbase = p0 + warp_m * 64 + mi * 16 + g;
#pragma unroll
        for (int half = 0; half < 2; half++) {
            int p = pbase + half * 8;
            int hp = p / PW, wp = p - hp * PW;
            if (hp < 1 || hp > 28 || wp < 1 || wp > 28) continue;
            size_t base = (size_t)n * CIN * HWPIX + (size_t)(hp - 1) * WW + (wp - 1);
#pragma unroll
            for (int ni = 0; ni < 8; ni++) {
                int co = warp_n * 64 + ni * 8 + 2 * tig;
                float sc0 = __ldg(g_scale + co), sc1 = __ldg(g_scale + co + 1);
                float bi0 = __ldg(g_bias + co),  bi1 = __ldg(g_bias + co + 1);
                float c0 = (float)acc[mi][ni][half * 2 + 0];
                float c1 = (float)acc[mi][ni][half * 2 + 1];
                float v0 = fminf(fmaxf(fmaf(c0, sc0, bi0), -1.f), 1.f);
                float v1 = fminf(fmaxf(fmaf(c1, sc1, bi1), -1.f), 1.f);
                size_t i0 = base + (size_t)co * HWPIX;
                size_t i1 = i0 + HWPIX;
                out[i0] = v0 + x[i0];
                out[i1] = v1 + x[i1];
            }
        }
    }
}

// ---------------- launch ----------------
extern "C" void kernel_launch(void* const* d_in, const int* in_sizes, int n_in,
                              void* d_out, int out_size) {
    const float* x     = (const float*)d_in[0];
    const float* w     = (const float*)d_in[1];
    const float* gamma = (const float*)d_in[2];
    const float* beta  = (const float*)d_in[3];
    const float* rmean = (const float*)d_in[4];
    const float* rvar  = (const float*)d_in[5];
    float* out = (float*)d_out;

    cudaFuncSetAttribute(imma_conv_kernel,
                         cudaFuncAttributeMaxDynamicSharedMemorySize, SMEM_TOTAL);

    {
        size_t total16 = (size_t)NB * PROWS * CIN / 16;
        zero_xpad_kernel<<<(unsigned)(total16 / 256), 256>>>();
    }
    pack_x_kernel<<<dim3(NB, HH), CIN>>>(x);
    pack_w_kernel<<<CIN, CIN>>>(w);
    bn_prep_kernel<<<1, CIN>>>(gamma, beta, rmean, rvar);

    imma_conv_kernel<<<dim3(NB, 7), TPB, SMEM_TOTAL>>>(x, out);
}

// round 4
// speedup vs baseline: 1.0692x; 1.0692x over previous
#include <cuda_runtime.h>
#include <cstdint>

#define NB 128
#define CIN 256
#define HH 28
#define WW 28
#define HWPIX 784
#define PW 30
#define PROWS 960
#define TAPS 9

#define BM 128
#define BN 128
#define BK 128
#define KBLOCKS 18
#define STAGES 3
#define TPB 256

#define A_BYTES (BM * BK)              // 16384
#define B_BYTES (BN * BK)              // 16384
#define STG_BYTES (A_BYTES + B_BYTES)  // 32768
#define SMEM_TOTAL (STAGES * STG_BYTES)

__device__ __align__(16) int8_t g_xpad[(size_t)NB * PROWS * CIN];  // padded NHWC signs
__device__ __align__(16) int8_t g_wmat[(size_t)CIN * TAPS * CIN];  // [co][tap*256+ci]
__device__ float g_scale[CIN];
__device__ float g_bias[CIN];

// ---------------- helpers ----------------
__device__ __forceinline__ uint32_t smem_u32(const void* p) {
    uint32_t a;
    asm("{ .reg .u64 t; cvta.to.shared.u64 t, %1; cvt.u32.u64 %0, t; }" : "=r"(a) : "l"(p));
    return a;
}

#define CP_ASYNC16(dst, src) \
    asm volatile("cp.async.cg.shared.global [%0], [%1], 16;" :: "r"(dst), "l"(src))
#define CP_COMMIT() asm volatile("cp.async.commit_group;" ::: "memory")
#define CP_WAIT(n)  asm volatile("cp.async.wait_group %0;" :: "n"(n) : "memory")

__device__ __forceinline__ void ldsm_x4(uint32_t* r, uint32_t addr) {
    asm volatile("ldmatrix.sync.aligned.m8n8.x4.shared.b16 {%0,%1,%2,%3}, [%4];"
                 : "=r"(r[0]), "=r"(r[1]), "=r"(r[2]), "=r"(r[3]) : "r"(addr));
}
__device__ __forceinline__ void ldsm_x2(uint32_t* r, uint32_t addr) {
    asm volatile("ldmatrix.sync.aligned.m8n8.x2.shared.b16 {%0,%1}, [%2];"
                 : "=r"(r[0]), "=r"(r[1]) : "r"(addr));
}
__device__ __forceinline__ void mma_s8(int* c, const uint32_t* a, const uint32_t* b) {
    asm volatile(
        "mma.sync.aligned.m16n8k32.row.col.s32.s8.s8.s32 "
        "{%0,%1,%2,%3}, {%4,%5,%6,%7}, {%8,%9}, {%0,%1,%2,%3};"
        : "+r"(c[0]), "+r"(c[1]), "+r"(c[2]), "+r"(c[3])
        : "r"(a[0]), "r"(a[1]), "r"(a[2]), "r"(a[3]), "r"(b[0]), "r"(b[1]));
}

// ---------------- prep kernels ----------------
__global__ void zero_xpad_kernel() {
    size_t i = (size_t)blockIdx.x * 256 + threadIdx.x;
    ((uint4*)g_xpad)[i] = make_uint4(0, 0, 0, 0);
}

__global__ void pack_x_kernel(const float* __restrict__ x) {
    int n = blockIdx.x, h = blockIdx.y, ci = threadIdx.x;
    const float* xp = x + ((size_t)(n * CIN + ci) * HH + h) * WW;
    int8_t* dst = g_xpad + ((size_t)n * PROWS + (size_t)(h + 1) * PW + 1) * CIN + ci;
#pragma unroll
    for (int w = 0; w < WW; w++) {
        float v = xp[w];
        dst[(size_t)w * CIN] = (v < 0.f) ? (int8_t)-1 : (v > 0.f ? (int8_t)1 : (int8_t)0);
    }
}

__global__ void pack_w_kernel(const float* __restrict__ w) {
    int co = blockIdx.x, ci = threadIdx.x;
    const float* wp = w + (size_t)(co * CIN + ci) * TAPS;
#pragma unroll
    for (int t = 0; t < TAPS; t++) {
        float v = wp[t];
        g_wmat[(size_t)co * (TAPS * CIN) + t * CIN + ci] =
            (v < 0.f) ? (int8_t)-1 : (v > 0.f ? (int8_t)1 : (int8_t)0);
    }
}

__global__ void bn_prep_kernel(const float* __restrict__ gamma, const float* __restrict__ beta,
                               const float* __restrict__ mean, const float* __restrict__ var) {
    int c = threadIdx.x;
    float inv = gamma[c] * rsqrtf(var[c] + 1e-5f);
    g_scale[c] = inv;
    g_bias[c] = beta[c] - mean[c] * inv;
}

// ---------------- loader: one K-block (tap, ch-half) into a stage ----------------
__device__ __forceinline__ void load_block(uint32_t stage, int n, int p0, int co0,
                                           int kb, int tid) {
    int t = kb >> 1, cb = kb & 1;
    int kh = t / 3, kw = t - kh * 3;
    int shift = (kh - 1) * PW + (kw - 1);
    const int8_t* abase = g_xpad + ((size_t)n * PROWS + p0 + shift) * CIN + cb * 128;
    // A: 128 rows x 128B
#pragma unroll
    for (int it = 0; it < 4; it++) {
        int ch = tid + it * 256;
        int row = ch >> 3, c = ch & 7;
        const int8_t* src = abase + (size_t)row * CIN + c * 16;
        uint32_t dst = stage + row * 128 + ((c ^ (row & 7)) << 4);
        CP_ASYNC16(dst, __cvta_generic_to_global(src));
    }
    // B: 128 rows x 128B
    const int8_t* bbase = g_wmat + (size_t)co0 * (TAPS * CIN) + t * CIN + cb * 128;
#pragma unroll
    for (int it = 0; it < 4; it++) {
        int ch = tid + it * 256;
        int row = ch >> 3, c = ch & 7;
        const int8_t* src = bbase + (size_t)row * (TAPS * CIN) + c * 16;
        uint32_t dst = stage + A_BYTES + row * 128 + ((c ^ (row & 7)) << 4);
        CP_ASYNC16(dst, __cvta_generic_to_global(src));
    }
}

// ---------------- main kernel ----------------
__global__ __launch_bounds__(TPB, 2)
void imma_conv_kernel(const float* __restrict__ x, float* __restrict__ out) {
    extern __shared__ __align__(1024) char smem[];
    uint32_t sb = smem_u32(smem);
    int tid = threadIdx.x;
    int lane = tid & 31, wid = tid >> 5;
    int warp_m = wid >> 1, warp_n = wid & 1;   // 4 x 2 warps, warp tile 32x64
    int n = blockIdx.x;
    int p0 = 31 + blockIdx.y * BM;
    int co0 = blockIdx.z * BN;

    // per-thread ldmatrix address components
    int s = lane & 7;                                 // swizzle key
    int rowA_l = (lane & 7) + ((lane >> 3) & 1) * 8;  // x4
    int cbitA = (lane >> 4) & 1;
    int rowB_l = lane & 7;                            // x2
    int cbitB = (lane >> 3) & 1;

    uint32_t aOff[2], bOff[8];
#pragma unroll
    for (int mi = 0; mi < 2; mi++)
        aOff[mi] = (warp_m * 32 + mi * 16 + rowA_l) * 128;
#pragma unroll
    for (int ni = 0; ni < 8; ni++)
        bOff[ni] = A_BYTES + (warp_n * 64 + ni * 8 + rowB_l) * 128;

    int acc[2][8][4];
#pragma unroll
    for (int mi = 0; mi < 2; mi++)
#pragma unroll
        for (int ni = 0; ni < 8; ni++)
#pragma unroll
            for (int r = 0; r < 4; r++) acc[mi][ni][r] = 0;

    // prologue
#pragma unroll
    for (int i = 0; i < STAGES; i++) {
        load_block(sb + i * STG_BYTES, n, p0, co0, i, tid);
        CP_COMMIT();
    }

    int sidx = 0;
    for (int i = 0; i < KBLOCKS; i++) {
        uint32_t stg = sb + sidx * STG_BYTES;
        sidx = (sidx == STAGES - 1) ? 0 : sidx + 1;
        CP_WAIT(2);
        __syncthreads();
#pragma unroll
        for (int kk = 0; kk < 4; kk++) {
            uint32_t a[2][4];
#pragma unroll
            for (int mi = 0; mi < 2; mi++)
                ldsm_x4(a[mi], stg + aOff[mi] + ((((kk * 2) + cbitA) ^ s) << 4));
            uint32_t b[8][2];
#pragma unroll
            for (int ni = 0; ni < 8; ni++)
                ldsm_x2(b[ni], stg + bOff[ni] + ((((kk * 2) + cbitB) ^ s) << 4));
#pragma unroll
            for (int mi = 0; mi < 2; mi++)
#pragma unroll
                for (int ni = 0; ni < 8; ni++)
                    mma_s8(acc[mi][ni], a[mi], b[ni]);
        }
        __syncthreads();
        if (i + STAGES < KBLOCKS)
            load_block(stg, n, p0, co0, i + STAGES, tid);
        CP_COMMIT();
    }

    // epilogue: BN + hardtanh + residual
    int g = lane >> 2, tig = lane & 3;
#pragma unroll
    for (int mi = 0; mi < 2; mi++) {
        int pbase = p0 + warp_m * 32 + mi * 16 + g;
#pragma unroll
        for (int half = 0; half < 2; half++) {
            int p = pbase + half * 8;
            int hp = p / PW, wp = p - hp * PW;
            if (hp < 1 || hp > 28 || wp < 1 || wp > 28) continue;
            size_t base = (size_t)n * CIN * HWPIX + (size_t)(hp - 1) * WW + (wp - 1);
#pragma unroll
            for (int ni = 0; ni < 8; ni++) {
                int co = co0 + warp_n * 64 + ni * 8 + 2 * tig;
                float sc0 = __ldg(g_scale + co), sc1 = __ldg(g_scale + co + 1);
                float bi0 = __ldg(g_bias + co),  bi1 = __ldg(g_bias + co + 1);
                float c0 = (float)acc[mi][ni][half * 2 + 0];
                float c1 = (float)acc[mi][ni][half * 2 + 1];
                float v0 = fminf(fmaxf(fmaf(c0, sc0, bi0), -1.f), 1.f);
                float v1 = fminf(fmaxf(fmaf(c1, sc1, bi1), -1.f), 1.f);
                size_t i0 = base + (size_t)co * HWPIX;
                size_t i1 = i0 + HWPIX;
                out[i0] = v0 + x[i0];
                out[i1] = v1 + x[i1];
            }
        }
    }
}

// ---------------- launch ----------------
extern "C" void kernel_launch(void* const* d_in, const int* in_sizes, int n_in,
                              void* d_out, int out_size) {
    const float* x     = (const float*)d_in[0];
    const float* w     = (const float*)d_in[1];
    const float* gamma = (const float*)d_in[2];
    const float* beta  = (const float*)d_in[3];
    const float* rmean = (const float*)d_in[4];
    const float* rvar  = (const float*)d_in[5];
    float* out = (float*)d_out;

    cudaFuncSetAttribute(imma_conv_kernel,
                         cudaFuncAttributeMaxDynamicSharedMemorySize, SMEM_TOTAL);

    {
        size_t total16 = (size_t)NB * PROWS * CIN / 16;
        zero_xpad_kernel<<<(unsigned)(total16 / 256), 256>>>();
    }
    pack_x_kernel<<<dim3(NB, HH), CIN>>>(x);
    pack_w_kernel<<<CIN, CIN>>>(w);
    bn_prep_kernel<<<1, CIN>>>(gamma, beta, rmean, rvar);

    imma_conv_kernel<<<dim3(NB, 7, 2), TPB, SMEM_TOTAL>>>(x, out);
}

// round 5
// speedup vs baseline: 1.4548x; 1.3606x over previous
#include <cuda_runtime.h>
#include <cstdint>

#define NB 128
#define CIN 256
#define HH 28
#define WW 28
#define HWPIX 784
#define PPOS 900        // 30x30 padded positions
#define TAPS 9
#define CW 8            // 256 ch / 32 bits

// scratch
__device__ __align__(16) uint32_t g_xpack[(size_t)NB * PPOS * CW];   // [n][pos][word], border = 0
__device__ __align__(16) uint32_t g_wpack[CIN * TAPS * CW];          // [co][tap][word]
__device__ float g_scale2[CIN];            // -2 * gamma/sqrt(var+eps)
__device__ float g_bias2[9 * CIN];         // per boundary-class fused bias

// ---------------- prep ----------------
__global__ void zero_xpack_kernel() {
    size_t i = (size_t)blockIdx.x * 256 + threadIdx.x;   // uint4 index
    ((uint4*)g_xpack)[i] = make_uint4(0, 0, 0, 0);
}

// grid (NB, HH), 224 threads: word = tid/28, w = tid%28
__global__ void pack_x_kernel(const float* __restrict__ x) {
    int n = blockIdx.x, hh = blockIdx.y;
    int word = threadIdx.x / 28, w = threadIdx.x % 28;
    const float* xp = x + ((size_t)(n * CIN + word * 32) * HH + hh) * WW + w;
    uint32_t bits = 0;
#pragma unroll
    for (int b = 0; b < 32; b++) {
        float v = xp[(size_t)b * HWPIX];
        bits |= (v < 0.f ? 1u : 0u) << b;
    }
    g_xpack[((size_t)n * PPOS + (hh + 1) * 30 + (w + 1)) * CW + word] = bits;
}

// grid CIN blocks, 72 threads: tap = tid/8, word = tid%8
__global__ void pack_w_kernel(const float* __restrict__ w) {
    int co = blockIdx.x;
    int tap = threadIdx.x / 8, word = threadIdx.x % 8;
    uint32_t bits = 0;
#pragma unroll
    for (int b = 0; b < 32; b++) {
        float v = w[((size_t)(co * CIN + word * 32 + b)) * TAPS + tap];
        bits |= (v < 0.f ? 1u : 0u) << b;
    }
    g_wpack[(co * TAPS + tap) * CW + word] = bits;
}

// after pack_w: fuse BN + boundary correction into scale2/bias2
__global__ void bn_prep_kernel(const float* __restrict__ gamma, const float* __restrict__ beta,
                               const float* __restrict__ mean, const float* __restrict__ var) {
    int co = threadIdx.x;
    float inv = gamma[co] * rsqrtf(var[co] + 1e-5f);
    float bias = beta[co] - mean[co] * inv;
    g_scale2[co] = -2.f * inv;
    int negw[TAPS];
#pragma unroll
    for (int t = 0; t < TAPS; t++) {
        int s = 0;
#pragma unroll
        for (int wd = 0; wd < CW; wd++) s += __popc(g_wpack[(co * TAPS + t) * CW + wd]);
        negw[t] = s;
    }
#pragma unroll
    for (int hv = 0; hv < 3; hv++) {
#pragma unroll
        for (int wv = 0; wv < 3; wv++) {
            int nv = 0, s = 0;
#pragma unroll
            for (int kh = 0; kh < 3; kh++) {
#pragma unroll
                for (int kw = 0; kw < 3; kw++) {
                    bool inval = (hv == 0 && kh == 0) || (hv == 2 && kh == 2) ||
                                 (wv == 0 && kw == 0) || (wv == 2 && kw == 2);
                    if (inval) s += negw[kh * 3 + kw];
                    else nv++;
                }
            }
            // true_conv = (256*nv + 2*sum_invalid_negw) - 2*acc_all9
            float convBase = 256.f * nv + 2.f * (float)s;
            g_bias2[(hv * 3 + wv) * CIN + co] = convBase * inv + bias;
        }
    }
}

// ---------------- main conv ----------------
// grid (NB, 16 co-groups of 16), block 224 = 2 cog8 x 112 pixel-threads
// thread: 7 pixels (quarter row) x 8 co
__global__ __launch_bounds__(224, 2)
void popc_conv_kernel(const float* __restrict__ x, float* __restrict__ out) {
    __shared__ uint32_t s_x[PPOS * CW];       // 28800 B
    __shared__ uint32_t s_w[16 * TAPS * CW];  // 4608 B
    int tid = threadIdx.x;
    int n = blockIdx.x, cg16 = blockIdx.y;

    {
        const uint4* xs = (const uint4*)(g_xpack + (size_t)n * PPOS * CW);
        uint4* xd = (uint4*)s_x;
        for (int i = tid; i < PPOS * CW / 4; i += 224) xd[i] = xs[i];
        const uint4* ws = (const uint4*)(g_wpack + (size_t)cg16 * 16 * TAPS * CW);
        uint4* wd = (uint4*)s_w;
        if (tid < 224) { for (int i = tid; i < 16 * TAPS * CW / 4; i += 224) wd[i] = ws[i]; }
    }
    __syncthreads();

    int cog8 = tid / 112, q = tid % 112;
    int h = q >> 2, w0 = 7 * (q & 3);

    int acc[7][8];
#pragma unroll
    for (int p = 0; p < 7; p++)
#pragma unroll
        for (int c = 0; c < 8; c++) acc[p][c] = 0;

#pragma unroll
    for (int kh = 0; kh < 3; kh++) {
#pragma unroll
        for (int wv = 0; wv < 2; wv++) {
            uint4 xq[9];
            int base = ((h + kh) * 30 + w0) * CW + wv * 4;
#pragma unroll
            for (int p = 0; p < 9; p++)
                xq[p] = *(const uint4*)&s_x[base + p * CW];
#pragma unroll
            for (int c = 0; c < 8; c++) {
#pragma unroll
                for (int kw = 0; kw < 3; kw++) {
                    uint4 wq = *(const uint4*)
                        &s_w[((cog8 * 8 + c) * TAPS + kh * 3 + kw) * CW + wv * 4];
#pragma unroll
                    for (int p = 0; p < 7; p++) {
                        uint4 xv = xq[p + kw];
                        acc[p][c] += __popc(xv.x ^ wq.x) + __popc(xv.y ^ wq.y)
                                   + __popc(xv.z ^ wq.z) + __popc(xv.w ^ wq.w);
                    }
                }
            }
        }
    }

    // epilogue: fused BN (+ boundary correction) + hardtanh + residual
    int hv = (h == 0) ? 0 : (h == 27 ? 2 : 1);
    int co_base = cg16 * 16 + cog8 * 8;
#pragma unroll
    for (int p = 0; p < 7; p++) {
        int w = w0 + p;
        int wvc = (w == 0) ? 0 : (w == 27 ? 2 : 1);
        int cls = hv * 3 + wvc;
#pragma unroll
        for (int c = 0; c < 8; c++) {
            int co = co_base + c;
            float s2 = __ldg(g_scale2 + co);
            float b2 = __ldg(g_bias2 + cls * CIN + co);
            float v = fminf(fmaxf(fmaf((float)acc[p][c], s2, b2), -1.f), 1.f);
            size_t idx = ((size_t)(n * CIN + co)) * HWPIX + h * WW + w;
            out[idx] = v + x[idx];
        }
    }
}

// ---------------- launch ----------------
extern "C" void kernel_launch(void* const* d_in, const int* in_sizes, int n_in,
                              void* d_out, int out_size) {
    const float* x     = (const float*)d_in[0];
    const float* w     = (const float*)d_in[1];
    const float* gamma = (const float*)d_in[2];
    const float* beta  = (const float*)d_in[3];
    const float* rmean = (const float*)d_in[4];
    const float* rvar  = (const float*)d_in[5];
    float* out = (float*)d_out;

    {   // zero xpack: 128*900*8 u32 = 230400 uint4
        zero_xpack_kernel<<<900, 256>>>();
    }
    pack_x_kernel<<<dim3(NB, HH), 224>>>(x);
    pack_w_kernel<<<CIN, 72>>>(w);
    bn_prep_kernel<<<1, CIN>>>(gamma, beta, rmean, rvar);

    popc_conv_kernel<<<dim3(NB, 16), 224>>>(x, out);
}

// round 6
// speedup vs baseline: 2.6047x; 1.7904x over previous
#include <cuda_runtime.h>
#include <cstdint>

#define NB 128
#define CIN 256
#define HH 28
#define WW 28
#define HWPIX 784
#define PPOS 900        // 30x30 padded positions
#define TAPS 9
#define CW 8            // 256 ch / 32 bits

// scratch
__device__ __align__(16) uint32_t g_xpack[(size_t)NB * PPOS * CW];   // [n][pos][word], border = 0
__device__ __align__(16) uint32_t g_wpack[CIN * TAPS * CW];          // [co][tap][word]
__device__ float g_scale2[CIN];            // -2 * gamma/sqrt(var+eps)
__device__ float g_bias2[9 * CIN];         // per boundary-class fused bias

// ---------------- prep ----------------
__global__ void zero_xpack_kernel() {
    size_t i = (size_t)blockIdx.x * 256 + threadIdx.x;   // uint4 index
    ((uint4*)g_xpack)[i] = make_uint4(0, 0, 0, 0);
}

// grid (NB, HH), 224 threads: word = tid/28, w = tid%28
__global__ void pack_x_kernel(const float* __restrict__ x) {
    int n = blockIdx.x, hh = blockIdx.y;
    int word = threadIdx.x / 28, w = threadIdx.x % 28;
    const float* xp = x + ((size_t)(n * CIN + word * 32) * HH + hh) * WW + w;
    uint32_t bits = 0;
#pragma unroll
    for (int b = 0; b < 32; b++) {
        float v = xp[(size_t)b * HWPIX];
        bits |= (v < 0.f ? 1u : 0u) << b;
    }
    g_xpack[((size_t)n * PPOS + (hh + 1) * 30 + (w + 1)) * CW + word] = bits;
}

// grid CIN blocks, 72 threads: tap = tid/8, word = tid%8
__global__ void pack_w_kernel(const float* __restrict__ w) {
    int co = blockIdx.x;
    int tap = threadIdx.x / 8, word = threadIdx.x % 8;
    uint32_t bits = 0;
#pragma unroll
    for (int b = 0; b < 32; b++) {
        float v = w[((size_t)(co * CIN + word * 32 + b)) * TAPS + tap];
        bits |= (v < 0.f ? 1u : 0u) << b;
    }
    g_wpack[(co * TAPS + tap) * CW + word] = bits;
}

// after pack_w: fuse BN + boundary correction into scale2/bias2
__global__ void bn_prep_kernel(const float* __restrict__ gamma, const float* __restrict__ beta,
                               const float* __restrict__ mean, const float* __restrict__ var) {
    int co = threadIdx.x;
    float inv = gamma[co] * rsqrtf(var[co] + 1e-5f);
    float bias = beta[co] - mean[co] * inv;
    g_scale2[co] = -2.f * inv;
    int negw[TAPS];
#pragma unroll
    for (int t = 0; t < TAPS; t++) {
        int s = 0;
#pragma unroll
        for (int wd = 0; wd < CW; wd++) s += __popc(g_wpack[(co * TAPS + t) * CW + wd]);
        negw[t] = s;
    }
#pragma unroll
    for (int hv = 0; hv < 3; hv++) {
#pragma unroll
        for (int wv = 0; wv < 3; wv++) {
            int nv = 0, s = 0;
#pragma unroll
            for (int kh = 0; kh < 3; kh++) {
#pragma unroll
                for (int kw = 0; kw < 3; kw++) {
                    bool inval = (hv == 0 && kh == 0) || (hv == 2 && kh == 2) ||
                                 (wv == 0 && kw == 0) || (wv == 2 && kw == 2);
                    if (inval) s += negw[kh * 3 + kw];
                    else nv++;
                }
            }
            float convBase = 256.f * nv + 2.f * (float)s;
            g_bias2[(hv * 3 + wv) * CIN + co] = convBase * inv + bias;
        }
    }
}

__global__ void dummy_kernel() {}

// full adder (3:2 compressor): 2 LOP3
__device__ __forceinline__ void fa(uint32_t a, uint32_t b, uint32_t c,
                                   uint32_t& s, uint32_t& cy) {
    s = a ^ b ^ c;
    cy = (a & b) | (c & (a | b));
}

// 12-word popcount via Harley-Seal: 7 FA + 5 POPC
__device__ __forceinline__ int popc12(const uint32_t* e) {
    uint32_t s0, c0, s1, c1, s2, c2, s3, c3, s4, c4, s5, d0, s6, d1;
    fa(e[0], e[1], e[2], s0, c0);
    fa(e[3], e[4], e[5], s1, c1);
    fa(e[6], e[7], e[8], s2, c2);
    fa(e[9], e[10], e[11], s3, c3);
    fa(s0, s1, s2, s4, c4);
    fa(c0, c1, c2, s5, d0);
    fa(s5, c3, c4, s6, d1);
    return __popc(s4) + __popc(s3) + 2 * __popc(s6) + 4 * (__popc(d0) + __popc(d1));
}

// ---------------- main conv ----------------
// grid (NB, 16 co-groups of 16), block 224 = 2 cog8 x 112 pixel-threads
// thread: 7 pixels (quarter row) x 8 co (4 packed pairs)
__global__ __launch_bounds__(224, 2)
void popc_conv_kernel(const float* __restrict__ x, float* __restrict__ out) {
    __shared__ uint32_t s_x[PPOS * CW];       // 28800 B
    __shared__ uint32_t s_w[16 * TAPS * CW];  // 4608 B
    int tid = threadIdx.x;
    int n = blockIdx.x, cg16 = blockIdx.y;

    {
        const uint4* xs = (const uint4*)(g_xpack + (size_t)n * PPOS * CW);
        uint4* xd = (uint4*)s_x;
        for (int i = tid; i < PPOS * CW / 4; i += 224) xd[i] = xs[i];
        const uint4* ws = (const uint4*)(g_wpack + (size_t)cg16 * 16 * TAPS * CW);
        uint4* wd = (uint4*)s_w;
        for (int i = tid; i < 16 * TAPS * CW / 4; i += 224) wd[i] = ws[i];
    }
    __syncthreads();

    int cog8 = tid / 112, q = tid % 112;
    int h = q >> 2, w0 = 7 * (q & 3);

    int acc[7][4];   // [pixel][co-pair], lo16 = even co, hi16 = odd co
#pragma unroll
    for (int p = 0; p < 7; p++)
#pragma unroll
        for (int cp = 0; cp < 4; cp++) acc[p][cp] = 0;

#pragma unroll 1
    for (int kh = 0; kh < 3; kh++) {
#pragma unroll 1
        for (int wv = 0; wv < 2; wv++) {
            uint4 xq[9];
            int xbase = ((h + kh) * 30 + w0) * CW + wv * 4;
#pragma unroll
            for (int i = 0; i < 9; i++)
                xq[i] = *(const uint4*)&s_x[xbase + i * CW];
#pragma unroll
            for (int cp = 0; cp < 4; cp++) {
                uint4 wqa[3], wqb[3];
                int wbase = ((cog8 * 8 + cp * 2) * TAPS + kh * 3) * CW + wv * 4;
#pragma unroll
                for (int kw = 0; kw < 3; kw++) {
                    wqa[kw] = *(const uint4*)&s_w[wbase + kw * CW];
                    wqb[kw] = *(const uint4*)&s_w[wbase + TAPS * CW + kw * CW];
                }
#pragma unroll
                for (int p = 0; p < 7; p++) {
                    uint32_t ea[12], eb[12];
#pragma unroll
                    for (int kw = 0; kw < 3; kw++) {
                        uint4 xv = xq[p + kw];
                        ea[kw * 4 + 0] = xv.x ^ wqa[kw].x;
                        ea[kw * 4 + 1] = xv.y ^ wqa[kw].y;
                        ea[kw * 4 + 2] = xv.z ^ wqa[kw].z;
                        ea[kw * 4 + 3] = xv.w ^ wqa[kw].w;
                        eb[kw * 4 + 0] = xv.x ^ wqb[kw].x;
                        eb[kw * 4 + 1] = xv.y ^ wqb[kw].y;
                        eb[kw * 4 + 2] = xv.z ^ wqb[kw].z;
                        eb[kw * 4 + 3] = xv.w ^ wqb[kw].w;
                    }
                    int ta = popc12(ea);
                    int tb = popc12(eb);
                    acc[p][cp] += ta + (tb << 16);
                }
            }
        }
    }

    // epilogue: fused BN (+ boundary correction) + hardtanh + residual
    int hv = (h == 0) ? 0 : (h == 27 ? 2 : 1);
    int co_base = cg16 * 16 + cog8 * 8;
#pragma unroll
    for (int p = 0; p < 7; p++) {
        int w = w0 + p;
        int wvc = (w == 0) ? 0 : (w == 27 ? 2 : 1);
        int cls = hv * 3 + wvc;
#pragma unroll
        for (int cp = 0; cp < 4; cp++) {
            int ca = acc[p][cp] & 0xFFFF;
            int cb = acc[p][cp] >> 16;
            int co = co_base + cp * 2;
            float s2a = __ldg(g_scale2 + co), s2b = __ldg(g_scale2 + co + 1);
            float b2a = __ldg(g_bias2 + cls * CIN + co);
            float b2b = __ldg(g_bias2 + cls * CIN + co + 1);
            float va = fminf(fmaxf(fmaf((float)ca, s2a, b2a), -1.f), 1.f);
            float vb = fminf(fmaxf(fmaf((float)cb, s2b, b2b), -1.f), 1.f);
            size_t idx = ((size_t)(n * CIN + co)) * HWPIX + h * WW + w;
            out[idx] = va + x[idx];
            out[idx + HWPIX] = vb + x[idx + HWPIX];
        }
    }
}

// ---------------- launch ----------------
extern "C" void kernel_launch(void* const* d_in, const int* in_sizes, int n_in,
                              void* d_out, int out_size) {
    const float* x     = (const float*)d_in[0];
    const float* w     = (const float*)d_in[1];
    const float* gamma = (const float*)d_in[2];
    const float* beta  = (const float*)d_in[3];
    const float* rmean = (const float*)d_in[4];
    const float* rvar  = (const float*)d_in[5];
    float* out = (float*)d_out;

    zero_xpack_kernel<<<900, 256>>>();                 // launch 0
    pack_x_kernel<<<dim3(NB, HH), 224>>>(x);           // launch 1
    pack_w_kernel<<<CIN, 72>>>(w);                     // launch 2
    bn_prep_kernel<<<1, CIN>>>(gamma, beta, rmean, rvar); // launch 3
    dummy_kernel<<<1, 32>>>();                         // launch 4 (aligns ncu -s 5 onto conv)
    popc_conv_kernel<<<dim3(NB, 16), 224>>>(x, out);   // launch 5  <-- profiled
}

// round 7
// speedup vs baseline: 2.7452x; 1.0540x over previous
#include <cuda_runtime.h>
#include <cstdint>

#define NB 128
#define CIN 256
#define HH 28
#define WW 28
#define HWPIX 784
#define PPOS 900        // 30x30 padded positions
#define TAPS 9
#define CW 8            // 256 ch / 32 bits

// scratch — zero-initialized at module load; border of g_xpack is never written,
// so it stays zero across all calls (interior rewritten every call).
__device__ __align__(16) uint32_t g_xpack[(size_t)NB * PPOS * CW];   // [n][pos][word]
__device__ __align__(16) uint32_t g_wpack[CIN * TAPS * CW];          // [co][tap][word]
__device__ float g_scale2[CIN];            // -2 * gamma/sqrt(var+eps)
__device__ float g_bias2[9 * CIN];         // per boundary-class fused bias

// ---------------- prep ----------------
// grid (NB, HH), 224 threads: word = tid/28, w = tid%28
__global__ void pack_x_kernel(const float* __restrict__ x) {
    int n = blockIdx.x, hh = blockIdx.y;
    int word = threadIdx.x / 28, w = threadIdx.x % 28;
    const float* xp = x + ((size_t)(n * CIN + word * 32) * HH + hh) * WW + w;
    uint32_t bits = 0;
#pragma unroll
    for (int b = 0; b < 32; b++) {
        float v = xp[(size_t)b * HWPIX];
        bits |= (v < 0.f ? 1u : 0u) << b;
    }
    g_xpack[((size_t)n * PPOS + (hh + 1) * 30 + (w + 1)) * CW + word] = bits;
}

// grid CIN blocks, 72 threads: tap = tid/8, word = tid%8
__global__ void pack_w_kernel(const float* __restrict__ w) {
    int co = blockIdx.x;
    int tap = threadIdx.x / 8, word = threadIdx.x % 8;
    uint32_t bits = 0;
#pragma unroll
    for (int b = 0; b < 32; b++) {
        float v = w[((size_t)(co * CIN + word * 32 + b)) * TAPS + tap];
        bits |= (v < 0.f ? 1u : 0u) << b;
    }
    g_wpack[(co * TAPS + tap) * CW + word] = bits;
}

// after pack_w: fuse BN + boundary correction into scale2/bias2
__global__ void bn_prep_kernel(const float* __restrict__ gamma, const float* __restrict__ beta,
                               const float* __restrict__ mean, const float* __restrict__ var) {
    int co = threadIdx.x;
    float inv = gamma[co] * rsqrtf(var[co] + 1e-5f);
    float bias = beta[co] - mean[co] * inv;
    g_scale2[co] = -2.f * inv;
    int negw[TAPS];
#pragma unroll
    for (int t = 0; t < TAPS; t++) {
        int s = 0;
#pragma unroll
        for (int wd = 0; wd < CW; wd++) s += __popc(g_wpack[(co * TAPS + t) * CW + wd]);
        negw[t] = s;
    }
#pragma unroll
    for (int hv = 0; hv < 3; hv++) {
#pragma unroll
        for (int wv = 0; wv < 3; wv++) {
            int nv = 0, s = 0;
#pragma unroll
            for (int kh = 0; kh < 3; kh++) {
#pragma unroll
                for (int kw = 0; kw < 3; kw++) {
                    bool inval = (hv == 0 && kh == 0) || (hv == 2 && kh == 2) ||
                                 (wv == 0 && kw == 0) || (wv == 2 && kw == 2);
                    if (inval) s += negw[kh * 3 + kw];
                    else nv++;
                }
            }
            float convBase = 256.f * nv + 2.f * (float)s;
            g_bias2[(hv * 3 + wv) * CIN + co] = convBase * inv + bias;
        }
    }
}

__global__ void dummy_kernel() {}

// full adder (3:2 compressor): 2 LOP3
__device__ __forceinline__ void fa(uint32_t a, uint32_t b, uint32_t c,
                                   uint32_t& s, uint32_t& cy) {
    s = a ^ b ^ c;
    cy = (a & b) | (c & (a | b));
}

// 12-word popcount, f=5 CSA tree (10 LOP3 + 7 POPC) — balanced for
// LOP3 rt=2 vs POPC rt=8 per SMSP.
__device__ __forceinline__ int popc12(const uint32_t* e) {
    uint32_t s0, c0, s1, c1, s2, c2, s3, c3, s4, c4;
    fa(e[0], e[1], e[2], s0, c0);
    fa(e[3], e[4], e[5], s1, c1);
    fa(e[6], e[7], e[8], s2, c2);
    fa(e[9], e[10], e[11], s3, c3);
    fa(s0, s1, s2, s4, c4);
    int w1 = __popc(s4) + __popc(s3);
    int w2 = __popc(c0) + __popc(c1) + __popc(c2) + __popc(c3) + __popc(c4);
    return w1 + 2 * w2;
}

// ---------------- main conv ----------------
// grid (NB, 16 co-groups of 16), block 224 = 2 cog8 x 112 pixel-threads
// thread: 7 pixels (quarter row) x 8 co (4 packed pairs)
__global__ __launch_bounds__(224, 2)
void popc_conv_kernel(const float* __restrict__ x, float* __restrict__ out) {
    __shared__ uint32_t s_x[PPOS * CW];       // 28800 B
    __shared__ uint32_t s_w[16 * TAPS * CW];  // 4608 B
    int tid = threadIdx.x;
    int n = blockIdx.x, cg16 = blockIdx.y;

    {
        const uint4* xs = (const uint4*)(g_xpack + (size_t)n * PPOS * CW);
        uint4* xd = (uint4*)s_x;
        for (int i = tid; i < PPOS * CW / 4; i += 224) xd[i] = xs[i];
        const uint4* ws = (const uint4*)(g_wpack + (size_t)cg16 * 16 * TAPS * CW);
        uint4* wd = (uint4*)s_w;
        for (int i = tid; i < 16 * TAPS * CW / 4; i += 224) wd[i] = ws[i];
    }
    __syncthreads();

    int cog8 = tid / 112, q = tid % 112;
    int h = q >> 2, w0 = 7 * (q & 3);

    int acc[7][4];   // [pixel][co-pair], lo16 = even co, hi16 = odd co
#pragma unroll
    for (int p = 0; p < 7; p++)
#pragma unroll
        for (int cp = 0; cp < 4; cp++) acc[p][cp] = 0;

#pragma unroll 1
    for (int kh = 0; kh < 3; kh++) {
#pragma unroll 1
        for (int wv = 0; wv < 2; wv++) {
            uint4 xq[9];
            int xbase = ((h + kh) * 30 + w0) * CW + wv * 4;
#pragma unroll
            for (int i = 0; i < 9; i++)
                xq[i] = *(const uint4*)&s_x[xbase + i * CW];
#pragma unroll
            for (int cp = 0; cp < 4; cp++) {
                uint4 wqa[3], wqb[3];
                int wbase = ((cog8 * 8 + cp * 2) * TAPS + kh * 3) * CW + wv * 4;
#pragma unroll
                for (int kw = 0; kw < 3; kw++) {
                    wqa[kw] = *(const uint4*)&s_w[wbase + kw * CW];
                    wqb[kw] = *(const uint4*)&s_w[wbase + TAPS * CW + kw * CW];
                }
#pragma unroll
                for (int p = 0; p < 7; p++) {
                    uint32_t ea[12], eb[12];
#pragma unroll
                    for (int kw = 0; kw < 3; kw++) {
                        uint4 xv = xq[p + kw];
                        ea[kw * 4 + 0] = xv.x ^ wqa[kw].x;
                        ea[kw * 4 + 1] = xv.y ^ wqa[kw].y;
                        ea[kw * 4 + 2] = xv.z ^ wqa[kw].z;
                        ea[kw * 4 + 3] = xv.w ^ wqa[kw].w;
                        eb[kw * 4 + 0] = xv.x ^ wqb[kw].x;
                        eb[kw * 4 + 1] = xv.y ^ wqb[kw].y;
                        eb[kw * 4 + 2] = xv.z ^ wqb[kw].z;
                        eb[kw * 4 + 3] = xv.w ^ wqb[kw].w;
                    }
                    int ta = popc12(ea);
                    int tb = popc12(eb);
                    acc[p][cp] += ta + (tb << 16);
                }
            }
        }
    }

    // epilogue: fused BN (+ boundary correction) + hardtanh + residual
    int hv = (h == 0) ? 0 : (h == 27 ? 2 : 1);
    int co_base = cg16 * 16 + cog8 * 8;
#pragma unroll
    for (int p = 0; p < 7; p++) {
        int w = w0 + p;
        int wvc = (w == 0) ? 0 : (w == 27 ? 2 : 1);
        int cls = hv * 3 + wvc;
#pragma unroll
        for (int cp = 0; cp < 4; cp++) {
            int ca = acc[p][cp] & 0xFFFF;
            int cb = acc[p][cp] >> 16;
            int co = co_base + cp * 2;
            float s2a = __ldg(g_scale2 + co), s2b = __ldg(g_scale2 + co + 1);
            float b2a = __ldg(g_bias2 + cls * CIN + co);
            float b2b = __ldg(g_bias2 + cls * CIN + co + 1);
            float va = fminf(fmaxf(fmaf((float)ca, s2a, b2a), -1.f), 1.f);
            float vb = fminf(fmaxf(fmaf((float)cb, s2b, b2b), -1.f), 1.f);
            size_t idx = ((size_t)(n * CIN + co)) * HWPIX + h * WW + w;
            out[idx] = va + x[idx];
            out[idx + HWPIX] = vb + x[idx + HWPIX];
        }
    }
}

// ---------------- launch ----------------
extern "C" void kernel_launch(void* const* d_in, const int* in_sizes, int n_in,
                              void* d_out, int out_size) {
    const float* x     = (const float*)d_in[0];
    const float* w     = (const float*)d_in[1];
    const float* gamma = (const float*)d_in[2];
    const float* beta  = (const float*)d_in[3];
    const float* rmean = (const float*)d_in[4];
    const float* rvar  = (const float*)d_in[5];
    float* out = (float*)d_out;

    pack_x_kernel<<<dim3(NB, HH), 224>>>(x);              // launch 0
    pack_w_kernel<<<CIN, 72>>>(w);                        // launch 1
    bn_prep_kernel<<<1, CIN>>>(gamma, beta, rmean, rvar); // launch 2
    dummy_kernel<<<1, 32>>>();                            // launch 3
    dummy_kernel<<<1, 32>>>();                            // launch 4
    popc_conv_kernel<<<dim3(NB, 16), 224>>>(x, out);      // launch 5  <-- ncu -s 5
}